// round 8
// baseline (speedup 1.0000x reference)
#include <cuda_runtime.h>
#include <cuda_bf16.h>
#include <cstdint>

// Problem constants
#define BB 4
#define SS 8192
#define DD 512
#define DFF 2048
#define NTOK (BB*SS)
#define KSEL 1024
#define MPAD 4096

// GEMM tiling
#define BM 128
#define BN 128
#define BK 32
#define LDA 40    // BK + 8 pad (bf16 units)
#define LDB 136   // BN + 8 pad

#define CP_ASYNC16(saddr, gptr) \
    asm volatile("cp.async.cg.shared.global [%0], [%1], 16;\n" :: "r"(saddr), "l"(gptr))
#define CP_COMMIT() asm volatile("cp.async.commit_group;\n" ::: "memory")
#define CP_WAIT(n)  asm volatile("cp.async.wait_group %0;\n" :: "n"(n) : "memory")

// ---------------- scratch (zero-initialized device globals; no allocation) ----------------
__device__ float g_weights[NTOK];
__device__ float g_thresh[BB];
__device__ int   g_count;
__device__ int   g_tok[MPAD];
__device__ float g_w[MPAD];
__device__ __nv_bfloat16 g_Xsel[MPAD * DD];      // 4 MB
__device__ __nv_bfloat16 g_H[MPAD * DFF];        // 16 MB
__device__ __nv_bfloat16 g_W1b[DD * DFF];        // 2 MB
__device__ __nv_bfloat16 g_W2b[DFF * DD];        // 2 MB

__device__ __forceinline__ float gelu_tanh(float a) {
    float a3 = a * a * a;
    float t = tanhf(0.7978845608028654f * (a + 0.044715f * a3));
    return 0.5f * a * (1.0f + t);
}

// ---------------- K0: convert W1, W2 to bf16 (vectorized: float4 in, 2x bf16x2 out) ----------------
__global__ void k_convert(const float* __restrict__ W1, const float* __restrict__ W2) {
    int i = blockIdx.x * blockDim.x + threadIdx.x;   // quad index
    if (i < DD * DFF / 4) {
        float4 a = ((const float4*)W1)[i];
        __nv_bfloat162 a0; a0.x = __float2bfloat16(a.x); a0.y = __float2bfloat16(a.y);
        __nv_bfloat162 a1; a1.x = __float2bfloat16(a.z); a1.y = __float2bfloat16(a.w);
        ((__nv_bfloat162*)g_W1b)[i * 2]     = a0;
        ((__nv_bfloat162*)g_W1b)[i * 2 + 1] = a1;
        float4 b = ((const float4*)W2)[i];
        __nv_bfloat162 b0; b0.x = __float2bfloat16(b.x); b0.y = __float2bfloat16(b.y);
        __nv_bfloat162 b1; b1.x = __float2bfloat16(b.z); b1.y = __float2bfloat16(b.w);
        ((__nv_bfloat162*)g_W2b)[i * 2]     = b0;
        ((__nv_bfloat162*)g_W2b)[i * 2 + 1] = b1;
    }
}

// ---------------- K1: router weights + copy x -> out + reset counter ----------------
__global__ void k_weights_copy(const float* __restrict__ x,
                               const float* __restrict__ Wr,
                               const float* __restrict__ br,
                               float* __restrict__ out) {
    int t = blockIdx.x;          // token
    int tid = threadIdx.x;       // 128 threads, 4 floats each
    if (t == 0 && tid == 0) g_count = 0;
    const float4 v = ((const float4*)(x + (size_t)t * DD))[tid];
    ((float4*)(out + (size_t)t * DD))[tid] = v;
    const float4 w4 = ((const float4*)Wr)[tid];
    float p = v.x * w4.x + v.y * w4.y + v.z * w4.z + v.w * w4.w;
    #pragma unroll
    for (int o = 16; o; o >>= 1) p += __shfl_down_sync(0xffffffffu, p, o);
    __shared__ float sp[4];
    if ((tid & 31) == 0) sp[tid >> 5] = p;
    __syncthreads();
    if (tid == 0) g_weights[t] = sp[0] + sp[1] + sp[2] + sp[3] + br[0];
}

// ---------------- K2: per-batch k-th largest via bitonic sort in smem ----------------
__global__ void k_thresh() {
    __shared__ float s[SS];
    int b = blockIdx.x, tid = threadIdx.x; // 1024 threads
    for (int i = tid; i < SS; i += 1024) s[i] = g_weights[b * SS + i];
    __syncthreads();
    for (int k = 2; k <= SS; k <<= 1) {
        for (int j = k >> 1; j > 0; j >>= 1) {
            for (int i = tid; i < SS; i += 1024) {
                int ixj = i ^ j;
                if (ixj > i) {
                    bool up = ((i & k) == 0);
                    float a = s[i], c = s[ixj];
                    if ((a > c) == up) { s[i] = c; s[ixj] = a; }
                }
            }
            __syncthreads();
        }
    }
    if (tid == 0) g_thresh[b] = s[SS - KSEL]; // ascending: k-th largest
}

// ---------------- K3: gather selected tokens -> bf16 X_sel (warp per token) ----------------
__global__ void k_gather(const float* __restrict__ x) {
    int gwarp = (blockIdx.x * blockDim.x + threadIdx.x) >> 5;
    int lane = threadIdx.x & 31;
    if (gwarp >= NTOK) return;
    int t = gwarp;
    float w = g_weights[t];
    int b = t >> 13; // t / SS
    if (!(w > g_thresh[b])) return;
    int slot;
    if (lane == 0) slot = atomicAdd(&g_count, 1);
    slot = __shfl_sync(0xffffffffu, slot, 0);
    if (lane == 0) { g_tok[slot] = t; g_w[slot] = w; }
    const float4* xr = (const float4*)(x + (size_t)t * DD);
    __nv_bfloat162* dst = (__nv_bfloat162*)(g_Xsel + (size_t)slot * DD);
    #pragma unroll
    for (int i = lane; i < DD / 4; i += 32) {
        float4 v = xr[i];
        __nv_bfloat162 h0; h0.x = __float2bfloat16(v.x); h0.y = __float2bfloat16(v.y);
        __nv_bfloat162 h1; h1.x = __float2bfloat16(v.z); h1.y = __float2bfloat16(v.w);
        dst[i * 2] = h0;
        dst[i * 2 + 1] = h1;
    }
}

// ---------------- GEMM (bf16 mma.sync, fp32 accum, cp.async double-buffered) ----------------
// FIRST:  H = gelu(Xsel @ W1 + b1)  [M=4096, N=2048, K=512], store bf16
// !FIRST: out[tok] = (H @ W2 + b2) * w   [M=4096, N=512, K=2048], guarded scatter
template<bool FIRST>
__global__ __launch_bounds__(256, 2) void k_gemm(const float* __restrict__ bias,
                                                 float* __restrict__ outF) {
    constexpr int N = FIRST ? DFF : DD;
    constexpr int KD = FIRST ? DD : DFF;
    constexpr int KT = KD / BK;
    const __nv_bfloat16* __restrict__ A  = FIRST ? g_Xsel : g_H;
    const __nv_bfloat16* __restrict__ Bm = FIRST ? g_W1b : g_W2b;

    __shared__ __nv_bfloat16 As[2][BM * LDA];
    __shared__ __nv_bfloat16 Bs[2][BK * LDB];

    int tid = threadIdx.x;
    int bm = blockIdx.y, bn = blockIdx.x;
    int lane = tid & 31, warp = tid >> 5;
    int wm = (warp & 1) * 64;   // warp row offset within tile
    int wn = (warp >> 1) * 32;  // warp col offset within tile

    float acc[4][4][4];
    #pragma unroll
    for (int i = 0; i < 4; i++)
        #pragma unroll
        for (int j = 0; j < 4; j++)
            #pragma unroll
            for (int c = 0; c < 4; c++) acc[i][j][c] = 0.f;

    // Per-thread source/dest coordinates for async copies (2 x 16B each for A and B)
    // A tile: 128 rows x 32 cols = 512 uint4; thread -> u = tid*2+j; r = u>>2, q = u&3
    // B tile: 32 rows x 128 cols = 512 uint4; thread -> u = tid*2+j; r = u>>4, q = u&15
    const __nv_bfloat16* Abase = A + (size_t)bm * BM * KD;

    auto load_tile = [&](int kt, int buf) {
        #pragma unroll
        for (int j = 0; j < 2; j++) {
            int u = tid * 2 + j;
            int r = u >> 2, q = u & 3;
            const __nv_bfloat16* src = Abase + (size_t)r * KD + kt * BK + q * 8;
            uint32_t dst = (uint32_t)__cvta_generic_to_shared(&As[buf][r * LDA + q * 8]);
            CP_ASYNC16(dst, src);
        }
        #pragma unroll
        for (int j = 0; j < 2; j++) {
            int u = tid * 2 + j;
            int r = u >> 4, q = u & 15;
            const __nv_bfloat16* src = Bm + (size_t)(kt * BK + r) * N + bn * BN + q * 8;
            uint32_t dst = (uint32_t)__cvta_generic_to_shared(&Bs[buf][r * LDB + q * 8]);
            CP_ASYNC16(dst, src);
        }
        CP_COMMIT();
    };

    load_tile(0, 0);

    for (int kt = 0; kt < KT; kt++) {
        int buf = kt & 1;
        if (kt + 1 < KT) {
            load_tile(kt + 1, buf ^ 1);
            CP_WAIT(1);   // retire current tile's group; prefetch stays in flight
        } else {
            CP_WAIT(0);
        }
        __syncthreads();

        #pragma unroll
        for (int ks = 0; ks < 2; ks++) {
            int k0 = ks * 16;
            uint32_t af[4][4], bf[4][2];
            #pragma unroll
            for (int mi = 0; mi < 4; mi++) {
                int row = wm + mi * 16 + (lane & 15);
                int col = k0 + ((lane >> 4) << 3);
                uint32_t addr = (uint32_t)__cvta_generic_to_shared(&As[buf][row * LDA + col]);
                asm volatile("ldmatrix.sync.aligned.m8n8.x4.shared.b16 {%0,%1,%2,%3},[%4];"
                    : "=r"(af[mi][0]), "=r"(af[mi][1]), "=r"(af[mi][2]), "=r"(af[mi][3])
                    : "r"(addr));
            }
            #pragma unroll
            for (int np = 0; np < 2; np++) {
                int row = k0 + (lane & 15);
                int col = wn + np * 16 + ((lane >> 4) << 3);
                uint32_t addr = (uint32_t)__cvta_generic_to_shared(&Bs[buf][row * LDB + col]);
                uint32_t r0, r1, r2, r3;
                asm volatile("ldmatrix.sync.aligned.m8n8.x4.trans.shared.b16 {%0,%1,%2,%3},[%4];"
                    : "=r"(r0), "=r"(r1), "=r"(r2), "=r"(r3) : "r"(addr));
                bf[np * 2][0] = r0; bf[np * 2][1] = r1;
                bf[np * 2 + 1][0] = r2; bf[np * 2 + 1][1] = r3;
            }
            #pragma unroll
            for (int mi = 0; mi < 4; mi++)
                #pragma unroll
                for (int ni = 0; ni < 4; ni++) {
                    asm volatile(
                        "mma.sync.aligned.m16n8k16.row.col.f32.bf16.bf16.f32 "
                        "{%0,%1,%2,%3},{%4,%5,%6,%7},{%8,%9},{%0,%1,%2,%3};"
                        : "+f"(acc[mi][ni][0]), "+f"(acc[mi][ni][1]),
                          "+f"(acc[mi][ni][2]), "+f"(acc[mi][ni][3])
                        : "r"(af[mi][0]), "r"(af[mi][1]), "r"(af[mi][2]), "r"(af[mi][3]),
                          "r"(bf[ni][0]), "r"(bf[ni][1]));
                }
        }
        __syncthreads();   // protect buf reuse by prefetch two iterations out
    }

    // epilogue
    int rbase = bm * BM + wm;
    int cbase = bn * BN + wn;
    int cnt = g_count;
    #pragma unroll
    for (int mi = 0; mi < 4; mi++) {
        #pragma unroll
        for (int half = 0; half < 2; half++) {
            int row = rbase + mi * 16 + (lane >> 2) + half * 8;
            if (FIRST) {
                #pragma unroll
                for (int ni = 0; ni < 4; ni++) {
                    int col = cbase + ni * 8 + (lane & 3) * 2;
                    float v0 = gelu_tanh(acc[mi][ni][half * 2 + 0] + bias[col]);
                    float v1 = gelu_tanh(acc[mi][ni][half * 2 + 1] + bias[col + 1]);
                    __nv_bfloat162 h; h.x = __float2bfloat16(v0); h.y = __float2bfloat16(v1);
                    *(__nv_bfloat162*)&g_H[(size_t)row * DFF + col] = h;
                }
            } else {
                if (row < cnt) {
                    int tok = g_tok[row];
                    float wgt = g_w[row];
                    #pragma unroll
                    for (int ni = 0; ni < 4; ni++) {
                        int col = cbase + ni * 8 + (lane & 3) * 2;
                        float v0 = (acc[mi][ni][half * 2 + 0] + bias[col]) * wgt;
                        float v1 = (acc[mi][ni][half * 2 + 1] + bias[col + 1]) * wgt;
                        float2 o; o.x = v0; o.y = v1;
                        *(float2*)&outF[(size_t)tok * DD + col] = o;
                    }
                }
            }
        }
    }
}

// ---------------- launch ----------------
extern "C" void kernel_launch(void* const* d_in, const int* in_sizes, int n_in,
                              void* d_out, int out_size) {
    const float* x  = (const float*)d_in[0];
    // d_in[1] = position_ids (unused)
    const float* Wr = (const float*)d_in[2];
    const float* br = (const float*)d_in[3];
    const float* W1 = (const float*)d_in[4];
    const float* b1 = (const float*)d_in[5];
    const float* W2 = (const float*)d_in[6];
    const float* b2 = (const float*)d_in[7];
    float* out = (float*)d_out;

    k_convert<<<(DD * DFF / 4 + 255) / 256, 256>>>(W1, W2);
    k_weights_copy<<<NTOK, 128>>>(x, Wr, br, out);
    k_thresh<<<BB, 1024>>>();
    k_gather<<<NTOK / 4, 128>>>(x);
    k_gemm<true><<<dim3(DFF / BN, MPAD / BM), 256>>>(b1, nullptr);
    k_gemm<false><<<dim3(DD / BN, MPAD / BM), 256>>>(b2, out);
}

// round 12
// speedup vs baseline: 1.1360x; 1.1360x over previous
#include <cuda_runtime.h>
#include <cuda_bf16.h>
#include <cstdint>

// Problem constants
#define BB 4
#define SS 8192
#define DD 512
#define DFF 2048
#define NTOK (BB*SS)
#define KSEL 1024
#define MPAD 4096

// GEMM tiling
#define BM 128
#define BN 128
#define BK 32
#define LDA 40    // BK + 8 pad (bf16 units)
#define LDB 136   // BN + 8 pad

// role-partition sizes
#define CONVBLK 512         // extra blocks in k_weights doing W1/W2 convert: 512 blk * 512 quads = DD*DFF/4
#define COPYY 8             // extra blockIdx.y rows in gemm1 doing x->out copy (8*16=128 blocks)

#define CP_ASYNC16(saddr, gptr) \
    asm volatile("cp.async.cg.shared.global [%0], [%1], 16;\n" :: "r"(saddr), "l"(gptr))
#define CP_COMMIT() asm volatile("cp.async.commit_group;\n" ::: "memory")
#define CP_WAIT(n)  asm volatile("cp.async.wait_group %0;\n" :: "n"(n) : "memory")

// ---------------- scratch (zero-initialized device globals; no allocation) ----------------
__device__ float g_weights[NTOK];
__device__ float g_thresh[BB];
__device__ int   g_count;
__device__ int   g_tok[MPAD];
__device__ float g_w[MPAD];
__device__ __nv_bfloat16 g_Xsel[MPAD * DD];      // 4 MB
__device__ __nv_bfloat16 g_H[MPAD * DFF];        // 16 MB
__device__ __nv_bfloat16 g_W1b[DD * DFF];        // 2 MB
__device__ __nv_bfloat16 g_W2b[DFF * DD];        // 2 MB

__device__ __forceinline__ float gelu_tanh(float a) {
    float a3 = a * a * a;
    float t = tanhf(0.7978845608028654f * (a + 0.044715f * a3));
    return 0.5f * a * (1.0f + t);
}

// ---------------- K1: router weights (+ fused W1/W2 convert role, + counter reset) ----------------
__global__ void k_weights(const float* __restrict__ x,
                          const float* __restrict__ Wr,
                          const float* __restrict__ br,
                          const float* __restrict__ W1,
                          const float* __restrict__ W2) {
    int bid = blockIdx.x;
    int tid = threadIdx.x;                 // 128 threads
    if (bid >= NTOK) {
        // ---- convert role: 512 blocks x 128 threads x 4 quads = DD*DFF/4 quads exactly ----
        int base = (bid - NTOK) * 512;
        #pragma unroll
        for (int j = 0; j < 4; j++) {
            int i = base + j * 128 + tid;  // quad index, lane-coalesced
            float4 a = ((const float4*)W1)[i];
            __nv_bfloat162 a0; a0.x = __float2bfloat16(a.x); a0.y = __float2bfloat16(a.y);
            __nv_bfloat162 a1; a1.x = __float2bfloat16(a.z); a1.y = __float2bfloat16(a.w);
            ((__nv_bfloat162*)g_W1b)[i * 2]     = a0;
            ((__nv_bfloat162*)g_W1b)[i * 2 + 1] = a1;
            float4 b = ((const float4*)W2)[i];
            __nv_bfloat162 b0; b0.x = __float2bfloat16(b.x); b0.y = __float2bfloat16(b.y);
            __nv_bfloat162 b1; b1.x = __float2bfloat16(b.z); b1.y = __float2bfloat16(b.w);
            ((__nv_bfloat162*)g_W2b)[i * 2]     = b0;
            ((__nv_bfloat162*)g_W2b)[i * 2 + 1] = b1;
        }
        return;
    }
    // ---- router role: one block per token ----
    int t = bid;
    if (t == 0 && tid == 0) g_count = 0;
    const float4 v = ((const float4*)(x + (size_t)t * DD))[tid];
    const float4 w4 = ((const float4*)Wr)[tid];
    float p = v.x * w4.x + v.y * w4.y + v.z * w4.z + v.w * w4.w;
    #pragma unroll
    for (int o = 16; o; o >>= 1) p += __shfl_down_sync(0xffffffffu, p, o);
    __shared__ float sp[4];
    if ((tid & 31) == 0) sp[tid >> 5] = p;
    __syncthreads();
    if (tid == 0) g_weights[t] = sp[0] + sp[1] + sp[2] + sp[3] + br[0];
}

// ---------------- K2: per-batch exact k-th largest via MSB-first radix select ----------------
// order-preserving map: neg -> ~bits, nonneg -> bits | 0x80000000 (unsigned ascending == float ascending)
__global__ void k_thresh() {
    __shared__ unsigned s_keys[SS];    // 32 KB
    __shared__ int hist[256];
    __shared__ int s_sel, s_kk;
    int b = blockIdx.x, tid = threadIdx.x;   // 1024 threads
    for (int i = tid; i < SS; i += 1024) {
        unsigned u = __float_as_uint(g_weights[b * SS + i]);
        s_keys[i] = (u & 0x80000000u) ? ~u : (u | 0x80000000u);
    }
    __syncthreads();
    unsigned prefix = 0, mask = 0;
    int k = KSEL;                             // find k-th largest key
    for (int shift = 24; shift >= 0; shift -= 8) {
        if (tid < 256) hist[tid] = 0;
        __syncthreads();
        for (int i = tid; i < SS; i += 1024) {
            unsigned u = s_keys[i];
            if ((u & mask) == prefix) atomicAdd(&hist[(u >> shift) & 0xFFu], 1);
        }
        __syncthreads();
        if (tid == 0) {
            int cum = 0, sel = 0;
            for (int d = 255; d >= 0; d--) {
                if (cum + hist[d] >= k) { sel = d; break; }
                cum += hist[d];
            }
            s_sel = sel; s_kk = k - cum;
        }
        __syncthreads();
        prefix |= ((unsigned)s_sel) << shift;
        mask   |= 0xFFu << shift;
        k = s_kk;
    }
    if (tid == 0) {
        unsigned u = prefix;   // exact key of the k-th largest element
        u = (u & 0x80000000u) ? (u & 0x7FFFFFFFu) : ~u;   // inverse transform
        g_thresh[b] = __uint_as_float(u);
    }
}

// ---------------- K3: gather selected tokens -> bf16 X_sel (warp per token) ----------------
__global__ void k_gather(const float* __restrict__ x) {
    int gwarp = (blockIdx.x * blockDim.x + threadIdx.x) >> 5;
    int lane = threadIdx.x & 31;
    if (gwarp >= NTOK) return;
    int t = gwarp;
    float w = g_weights[t];
    int b = t >> 13; // t / SS
    if (!(w > g_thresh[b])) return;
    int slot;
    if (lane == 0) slot = atomicAdd(&g_count, 1);
    slot = __shfl_sync(0xffffffffu, slot, 0);
    if (lane == 0) { g_tok[slot] = t; g_w[slot] = w; }
    const float4* xr = (const float4*)(x + (size_t)t * DD);
    __nv_bfloat162* dst = (__nv_bfloat162*)(g_Xsel + (size_t)slot * DD);
    #pragma unroll
    for (int i = lane; i < DD / 4; i += 32) {
        float4 v = xr[i];
        __nv_bfloat162 h0; h0.x = __float2bfloat16(v.x); h0.y = __float2bfloat16(v.y);
        __nv_bfloat162 h1; h1.x = __float2bfloat16(v.z); h1.y = __float2bfloat16(v.w);
        dst[i * 2] = h0;
        dst[i * 2 + 1] = h1;
    }
}

// ---------------- GEMM (bf16 mma.sync, fp32 accum, cp.async double-buffered) ----------------
// FIRST:  H = gelu(Xsel @ W1 + b1)  [M=4096, N=2048, K=512]  + copy-role blocks (x -> out)
// !FIRST: out[tok] = (H @ W2 + b2) * w   [M=4096, N=512, K=2048], guarded scatter
template<bool FIRST>
__global__ __launch_bounds__(256, 2) void k_gemm(const float* __restrict__ bias,
                                                 float* __restrict__ outF,
                                                 const float* __restrict__ xIn) {
    if (FIRST && blockIdx.y >= (MPAD / BM)) {
        // ---- copy role: x -> out, 128 blocks x 256 threads, hidden under GEMM1 compute ----
        int cb = (blockIdx.y - (MPAD / BM)) * gridDim.x + blockIdx.x;   // 0..127
        const float4* src = (const float4*)xIn;
        float4* dst = (float4*)outF;
        const int total = NTOK * DD / 4;
        for (int i = cb * 256 + threadIdx.x; i < total; i += 128 * 256)
            dst[i] = src[i];
        return;
    }

    constexpr int N = FIRST ? DFF : DD;
    constexpr int KD = FIRST ? DD : DFF;
    constexpr int KT = KD / BK;
    const __nv_bfloat16* __restrict__ A  = FIRST ? g_Xsel : g_H;
    const __nv_bfloat16* __restrict__ Bm = FIRST ? g_W1b : g_W2b;

    __shared__ __nv_bfloat16 As[2][BM * LDA];
    __shared__ __nv_bfloat16 Bs[2][BK * LDB];

    int tid = threadIdx.x;
    int bm = blockIdx.y, bn = blockIdx.x;
    int lane = tid & 31, warp = tid >> 5;
    int wm = (warp & 1) * 64;   // warp row offset within tile
    int wn = (warp >> 1) * 32;  // warp col offset within tile

    float acc[4][4][4];
    #pragma unroll
    for (int i = 0; i < 4; i++)
        #pragma unroll
        for (int j = 0; j < 4; j++)
            #pragma unroll
            for (int c = 0; c < 4; c++) acc[i][j][c] = 0.f;

    const __nv_bfloat16* Abase = A + (size_t)bm * BM * KD;

    auto load_tile = [&](int kt, int buf) {
        #pragma unroll
        for (int j = 0; j < 2; j++) {
            int u = tid * 2 + j;
            int r = u >> 2, q = u & 3;
            const __nv_bfloat16* src = Abase + (size_t)r * KD + kt * BK + q * 8;
            uint32_t dst = (uint32_t)__cvta_generic_to_shared(&As[buf][r * LDA + q * 8]);
            CP_ASYNC16(dst, src);
        }
        #pragma unroll
        for (int j = 0; j < 2; j++) {
            int u = tid * 2 + j;
            int r = u >> 4, q = u & 15;
            const __nv_bfloat16* src = Bm + (size_t)(kt * BK + r) * N + bn * BN + q * 8;
            uint32_t dst = (uint32_t)__cvta_generic_to_shared(&Bs[buf][r * LDB + q * 8]);
            CP_ASYNC16(dst, src);
        }
        CP_COMMIT();
    };

    load_tile(0, 0);

    for (int kt = 0; kt < KT; kt++) {
        int buf = kt & 1;
        if (kt + 1 < KT) {
            load_tile(kt + 1, buf ^ 1);
            CP_WAIT(1);   // retire current tile's group; prefetch stays in flight
        } else {
            CP_WAIT(0);
        }
        __syncthreads();

        #pragma unroll
        for (int ks = 0; ks < 2; ks++) {
            int k0 = ks * 16;
            uint32_t af[4][4], bf[4][2];
            #pragma unroll
            for (int mi = 0; mi < 4; mi++) {
                int row = wm + mi * 16 + (lane & 15);
                int col = k0 + ((lane >> 4) << 3);
                uint32_t addr = (uint32_t)__cvta_generic_to_shared(&As[buf][row * LDA + col]);
                asm volatile("ldmatrix.sync.aligned.m8n8.x4.shared.b16 {%0,%1,%2,%3},[%4];"
                    : "=r"(af[mi][0]), "=r"(af[mi][1]), "=r"(af[mi][2]), "=r"(af[mi][3])
                    : "r"(addr));
            }
            #pragma unroll
            for (int np = 0; np < 2; np++) {
                int row = k0 + (lane & 15);
                int col = wn + np * 16 + ((lane >> 4) << 3);
                uint32_t addr = (uint32_t)__cvta_generic_to_shared(&Bs[buf][row * LDB + col]);
                uint32_t r0, r1, r2, r3;
                asm volatile("ldmatrix.sync.aligned.m8n8.x4.trans.shared.b16 {%0,%1,%2,%3},[%4];"
                    : "=r"(r0), "=r"(r1), "=r"(r2), "=r"(r3) : "r"(addr));
                bf[np * 2][0] = r0; bf[np * 2][1] = r1;
                bf[np * 2 + 1][0] = r2; bf[np * 2 + 1][1] = r3;
            }
            #pragma unroll
            for (int mi = 0; mi < 4; mi++)
                #pragma unroll
                for (int ni = 0; ni < 4; ni++) {
                    asm volatile(
                        "mma.sync.aligned.m16n8k16.row.col.f32.bf16.bf16.f32 "
                        "{%0,%1,%2,%3},{%4,%5,%6,%7},{%8,%9},{%0,%1,%2,%3};"
                        : "+f"(acc[mi][ni][0]), "+f"(acc[mi][ni][1]),
                          "+f"(acc[mi][ni][2]), "+f"(acc[mi][ni][3])
                        : "r"(af[mi][0]), "r"(af[mi][1]), "r"(af[mi][2]), "r"(af[mi][3]),
                          "r"(bf[ni][0]), "r"(bf[ni][1]));
                }
        }
        __syncthreads();   // protect buf reuse by prefetch two iterations out
    }

    // epilogue
    int rbase = bm * BM + wm;
    int cbase = bn * BN + wn;
    int cnt = g_count;
    #pragma unroll
    for (int mi = 0; mi < 4; mi++) {
        #pragma unroll
        for (int half = 0; half < 2; half++) {
            int row = rbase + mi * 16 + (lane >> 2) + half * 8;
            if (FIRST) {
                #pragma unroll
                for (int ni = 0; ni < 4; ni++) {
                    int col = cbase + ni * 8 + (lane & 3) * 2;
                    float v0 = gelu_tanh(acc[mi][ni][half * 2 + 0] + bias[col]);
                    float v1 = gelu_tanh(acc[mi][ni][half * 2 + 1] + bias[col + 1]);
                    __nv_bfloat162 h; h.x = __float2bfloat16(v0); h.y = __float2bfloat16(v1);
                    *(__nv_bfloat162*)&g_H[(size_t)row * DFF + col] = h;
                }
            } else {
                if (row < cnt) {
                    int tok = g_tok[row];
                    float wgt = g_w[row];
                    #pragma unroll
                    for (int ni = 0; ni < 4; ni++) {
                        int col = cbase + ni * 8 + (lane & 3) * 2;
                        float v0 = (acc[mi][ni][half * 2 + 0] + bias[col]) * wgt;
                        float v1 = (acc[mi][ni][half * 2 + 1] + bias[col + 1]) * wgt;
                        float2 o; o.x = v0; o.y = v1;
                        *(float2*)&outF[(size_t)tok * DD + col] = o;
                    }
                }
            }
        }
    }
}

// ---------------- launch ----------------
extern "C" void kernel_launch(void* const* d_in, const int* in_sizes, int n_in,
                              void* d_out, int out_size) {
    const float* x  = (const float*)d_in[0];
    // d_in[1] = position_ids (unused)
    const float* Wr = (const float*)d_in[2];
    const float* br = (const float*)d_in[3];
    const float* W1 = (const float*)d_in[4];
    const float* b1 = (const float*)d_in[5];
    const float* W2 = (const float*)d_in[6];
    const float* b2 = (const float*)d_in[7];
    float* out = (float*)d_out;

    k_weights<<<NTOK + CONVBLK, 128>>>(x, Wr, br, W1, W2);
    k_thresh<<<BB, 1024>>>();
    k_gather<<<NTOK / 4, 128>>>(x);
    k_gemm<true><<<dim3(DFF / BN, MPAD / BM + COPYY), 256>>>(b1, out, x);
    k_gemm<false><<<dim3(DD / BN, MPAD / BM), 256>>>(b2, out, x);
}